// round 3
// baseline (speedup 1.0000x reference)
#include <cuda_runtime.h>
#include <cstdint>

#define NNODES 100000
#define KF     48

// scratch: [x_pos | x_neg], each NNODES*KF floats
__device__ float g_scratch[2u * NNODES * KF];
// dtype flag: 1 if edge indices are int64, 0 if int32
__device__ int g_is64;

// ---------------------------------------------------------------------------
// Kernel 0: probe index dtype. For int64 values in [0, 1e5), every odd 32-bit
// word (high half, little-endian) is zero. For int32 random indices, sampled
// odd words are ~never all zero. Deterministic given the input data.
// ---------------------------------------------------------------------------
__global__ void probe_kernel(const unsigned int* __restrict__ p, int n_idx) {
    __shared__ int any_nonzero;
    if (threadIdx.x == 0) any_nonzero = 0;
    __syncthreads();
    // sample up to 4096 "odd word" positions spread across the buffer
    int stride = n_idx / 4096;
    if (stride < 1) stride = 1;
    for (int i = threadIdx.x; i < 4096; i += blockDim.x) {
        long long w = (long long)i * stride;
        if (w >= n_idx) break;
        if (p[2 * w + 1] != 0u) any_nonzero = 1;   // benign race (writes 1)
    }
    __syncthreads();
    if (threadIdx.x == 0) g_is64 = any_nonzero ? 0 : 1;
}

// ---------------------------------------------------------------------------
// Kernel 1: zero the scatter accumulators (float4 stores)
// ---------------------------------------------------------------------------
__global__ void zero_scratch_kernel(int n4) {
    int i = blockIdx.x * blockDim.x + threadIdx.x;
    if (i < n4) {
        ((float4*)g_scratch)[i] = make_float4(0.f, 0.f, 0.f, 0.f);
    }
}

// ---------------------------------------------------------------------------
// Kernel 2: edge scatter-add. 4 lanes cooperate per edge; each lane handles
// 3 float4 chunks (cols 4q, 4q+16, 4q+32). Handles BOTH edge sets in one
// grid: global edge id in [0, 2E): [0,E) -> pos, [E,2E) -> neg.
// red.global.add.v4.f32 (sm_90+) cuts atomic op count 4x vs scalar.
// ---------------------------------------------------------------------------
__global__ void scatter_kernel(const float* __restrict__ x,
                               const void* __restrict__ pos_idx,
                               const void* __restrict__ neg_idx,
                               int E) {
    long long gid = (long long)blockIdx.x * blockDim.x + threadIdx.x;
    int q = (int)(gid & 3);
    long long eg = gid >> 2;
    if (eg >= 2LL * E) return;

    const void* idx;
    float* outbase;
    long long e;
    if (eg < E) {
        idx = pos_idx; outbase = g_scratch; e = eg;
    } else {
        idx = neg_idx; outbase = g_scratch + (size_t)NNODES * KF; e = eg - E;
    }

    int src, dst;
    if (g_is64) {
        const long long* p = (const long long*)idx;
        src = (int)p[e];
        dst = (int)p[e + E];
    } else {
        const int* p = (const int*)idx;
        src = p[e];
        dst = p[e + E];
    }

    const float4* xr = (const float4*)(x + (size_t)src * KF);
    float* orow = outbase + (size_t)dst * KF;

#pragma unroll
    for (int k = 0; k < 3; k++) {
        float4 v = xr[q + 4 * k];               // float cols 4q + 16k .. +3
        float* addr = orow + 4 * q + 16 * k;    // 16B aligned (row = 192B)
        asm volatile(
            "red.global.add.v4.f32 [%0], {%1, %2, %3, %4};"
            :: "l"(addr), "f"(v.x), "f"(v.y), "f"(v.z), "f"(v.w)
            : "memory");
    }
}

// ---------------------------------------------------------------------------
// Kernel 3: per-node fused MLP + softmax.
//   in = [x_n | xpos_n | xneg_n]  (144 floats)
//   h  = tanh(in @ W1 + b1)       (16)
//   C  = h @ W2 + b2              (48)
//   out = softmax(C)
// Thread-per-node; weights staged in shared (warp-uniform LDS = broadcast).
// ---------------------------------------------------------------------------
__global__ void __launch_bounds__(128)
node_kernel(const float* __restrict__ x,
            const float* __restrict__ W1,
            const float* __restrict__ b1,
            const float* __restrict__ W2,
            const float* __restrict__ b2,
            float* __restrict__ out,
            int N) {
    __shared__ float W1s[144 * 16];
    __shared__ float W2s[16 * 48];
    __shared__ float b1s[16];
    __shared__ float b2s[48];

    for (int i = threadIdx.x; i < 144 * 16; i += blockDim.x) W1s[i] = W1[i];
    for (int i = threadIdx.x; i < 16 * 48;  i += blockDim.x) W2s[i] = W2[i];
    if (threadIdx.x < 16) b1s[threadIdx.x] = b1[threadIdx.x];
    if (threadIdx.x < 48) b2s[threadIdx.x] = b2[threadIdx.x];
    __syncthreads();

    int n = blockIdx.x * blockDim.x + threadIdx.x;
    if (n >= N) return;

    float h[16];
#pragma unroll
    for (int j = 0; j < 16; j++) h[j] = b1s[j];

    const float* src0 = x + (size_t)n * KF;
    const float* src1 = g_scratch + (size_t)n * KF;
    const float* src2 = g_scratch + (size_t)(NNODES + n) * KF;

    for (int s = 0; s < 3; s++) {
        const float* sp = (s == 0) ? src0 : (s == 1) ? src1 : src2;
        const float4* sp4 = (const float4*)sp;
        for (int c = 0; c < 12; c++) {
            float4 v = sp4[c];
            const float* w = &W1s[(s * 48 + c * 4) * 16];
#pragma unroll
            for (int j = 0; j < 16; j++) h[j] += v.x * w[j];
#pragma unroll
            for (int j = 0; j < 16; j++) h[j] += v.y * w[16 + j];
#pragma unroll
            for (int j = 0; j < 16; j++) h[j] += v.z * w[32 + j];
#pragma unroll
            for (int j = 0; j < 16; j++) h[j] += v.w * w[48 + j];
        }
    }

#pragma unroll
    for (int j = 0; j < 16; j++) h[j] = tanhf(h[j]);

    float C[48];
#pragma unroll
    for (int c = 0; c < 48; c++) C[c] = b2s[c];
    for (int j = 0; j < 16; j++) {
        float hj = h[j];
        const float* w = &W2s[j * 48];
#pragma unroll
        for (int c = 0; c < 48; c++) C[c] += hj * w[c];
    }

    // softmax over the 48 columns
    float m = C[0];
#pragma unroll
    for (int c = 1; c < 48; c++) m = fmaxf(m, C[c]);
    float sum = 0.f;
#pragma unroll
    for (int c = 0; c < 48; c++) { C[c] = __expf(C[c] - m); sum += C[c]; }
    float inv = 1.0f / sum;
#pragma unroll
    for (int c = 0; c < 48; c++) C[c] *= inv;

    float4* o4 = (float4*)(out + (size_t)n * KF);
#pragma unroll
    for (int c = 0; c < 12; c++)
        o4[c] = make_float4(C[4 * c], C[4 * c + 1], C[4 * c + 2], C[4 * c + 3]);
}

// ---------------------------------------------------------------------------
// Launch
// inputs: 0:x [N,48] f32, 1:pos_edge_index [2,E] int, 2:neg_edge_index [2,E] int,
//         3:W1 [144,16] f32, 4:b1 [16] f32, 5:W2 [16,48] f32, 6:b2 [48] f32
// output: [N,48] f32
// ---------------------------------------------------------------------------
extern "C" void kernel_launch(void* const* d_in, const int* in_sizes, int n_in,
                              void* d_out, int out_size) {
    const float* x   = (const float*)d_in[0];
    const void*  pos = d_in[1];
    const void*  neg = d_in[2];
    const float* W1  = (const float*)d_in[3];
    const float* b1  = (const float*)d_in[4];
    const float* W2  = (const float*)d_in[5];
    const float* b2  = (const float*)d_in[6];
    float* out = (float*)d_out;

    int N = in_sizes[0] / KF;          // 100000
    int E = in_sizes[1] / 2;           // 1600000

    // 0) probe index dtype (int32 vs int64)
    probe_kernel<<<1, 256>>>((const unsigned int*)pos, E);

    // 1) zero accumulators
    int n4 = 2 * NNODES * KF / 4;
    zero_scratch_kernel<<<(n4 + 255) / 256, 256>>>(n4);

    // 2) scatter-add both edge sets (4 lanes / edge)
    long long total = 2LL * E * 4;
    int blocks = (int)((total + 255) / 256);
    scatter_kernel<<<blocks, 256>>>(x, pos, neg, E);

    // 3) fused MLP + softmax per node
    node_kernel<<<(N + 127) / 128, 128>>>(x, W1, b1, W2, b2, out, N);
}

// round 4
// speedup vs baseline: 1.0323x; 1.0323x over previous
#include <cuda_runtime.h>
#include <cstdint>

#define NNODES 100000
#define KF     48

// scratch: [x_pos | x_neg], each NNODES*KF floats
__device__ float g_scratch[2u * NNODES * KF];
// dtype flag: 1 if edge indices are int64, 0 if int32
__device__ int g_is64;

// ---- packed f32x2 helpers (Blackwell FFMA2 path; ptxas never auto-fuses) ----
#define PACK_F32X2(out, lo, hi) \
    asm("mov.b64 %0, {%1, %2};" : "=l"(out) : "f"(lo), "f"(hi))
#define UNPACK_F32X2(lo, hi, in) \
    asm("mov.b64 {%0, %1}, %2;" : "=f"(lo), "=f"(hi) : "l"(in))
#define FMA_F32X2(d, a, b) \
    asm("fma.rn.f32x2 %0, %1, %2, %3;" : "=l"(d) : "l"(a), "l"(b), "l"(d))

// ---------------------------------------------------------------------------
// Kernel 1: zero the scatter accumulators (float4 stores) + dtype probe
// (block 0 only). For int64 indices in [0,1e5) every odd 32-bit word is 0;
// for int32 random indices sampled odd words are ~never all zero.
// ---------------------------------------------------------------------------
__global__ void zero_probe_kernel(const unsigned int* __restrict__ p,
                                  int n_idx, int n4) {
    int i = blockIdx.x * blockDim.x + threadIdx.x;
    if (i < n4) {
        ((float4*)g_scratch)[i] = make_float4(0.f, 0.f, 0.f, 0.f);
    }
    if (blockIdx.x == 0) {
        __shared__ int any_nonzero;
        if (threadIdx.x == 0) any_nonzero = 0;
        __syncthreads();
        int stride = n_idx / 4096;
        if (stride < 1) stride = 1;
        for (int s = threadIdx.x; s < 4096; s += blockDim.x) {
            long long w = (long long)s * stride;
            if (w >= n_idx) break;
            if (p[2 * w + 1] != 0u) any_nonzero = 1;   // benign race
        }
        __syncthreads();
        if (threadIdx.x == 0) g_is64 = any_nonzero ? 0 : 1;
    }
}

// ---------------------------------------------------------------------------
// Kernel 2: edge scatter-add. 4 lanes cooperate per edge; each lane handles
// 3 float4 chunks. Global edge id in [0, 2E): [0,E)->pos, [E,2E)->neg.
// red.global.add.v4.f32 cuts atomic op count 4x vs scalar.
// ---------------------------------------------------------------------------
__global__ void scatter_kernel(const float* __restrict__ x,
                               const void* __restrict__ pos_idx,
                               const void* __restrict__ neg_idx,
                               int E) {
    long long gid = (long long)blockIdx.x * blockDim.x + threadIdx.x;
    int q = (int)(gid & 3);
    long long eg = gid >> 2;
    if (eg >= 2LL * E) return;

    const void* idx;
    float* outbase;
    long long e;
    if (eg < E) {
        idx = pos_idx; outbase = g_scratch; e = eg;
    } else {
        idx = neg_idx; outbase = g_scratch + (size_t)NNODES * KF; e = eg - E;
    }

    int src, dst;
    if (g_is64) {
        const long long* p = (const long long*)idx;
        src = (int)p[e];
        dst = (int)p[e + E];
    } else {
        const int* p = (const int*)idx;
        src = p[e];
        dst = p[e + E];
    }

    const float4* xr = (const float4*)(x + (size_t)src * KF);
    float* orow = outbase + (size_t)dst * KF;

#pragma unroll
    for (int k = 0; k < 3; k++) {
        float4 v = xr[q + 4 * k];
        float* addr = orow + 4 * q + 16 * k;    // 16B aligned (row = 192B)
        asm volatile(
            "red.global.add.v4.f32 [%0], {%1, %2, %3, %4};"
            :: "l"(addr), "f"(v.x), "f"(v.y), "f"(v.z), "f"(v.w)
            : "memory");
    }
}

// ---------------------------------------------------------------------------
// Kernel 3: per-node fused MLP + softmax, packed-f32x2 math.
//   in = [x_n | xpos_n | xneg_n] (144)  ->  h = tanh(in@W1+b1) (16)
//   C  = h@W2 + b2 (48)  ->  out = softmax(C)
// h kept as 8 packed f32x2, C as 24 packed f32x2. Weights staged in shared,
// read as ulonglong2 (LDS.128 = 2 packed operands per load, warp-uniform
// broadcast -> conflict-free).
// ---------------------------------------------------------------------------
__global__ void __launch_bounds__(128, 3)
node_kernel(const float* __restrict__ x,
            const float* __restrict__ W1,
            const float* __restrict__ b1,
            const float* __restrict__ W2,
            const float* __restrict__ b2,
            float* __restrict__ out,
            int N) {
    __shared__ float W1s[144 * 16];   // row-major [144][16], rows 64B-aligned
    __shared__ float W2s[16 * 48];    // row-major [16][48],  rows 16B-aligned
    __shared__ float b1s[16];
    __shared__ float b2s[48];

    for (int i = threadIdx.x; i < 144 * 16; i += blockDim.x) W1s[i] = W1[i];
    for (int i = threadIdx.x; i < 16 * 48;  i += blockDim.x) W2s[i] = W2[i];
    if (threadIdx.x < 16) b1s[threadIdx.x] = b1[threadIdx.x];
    if (threadIdx.x < 48) b2s[threadIdx.x] = b2[threadIdx.x];
    __syncthreads();

    int n = blockIdx.x * blockDim.x + threadIdx.x;
    if (n >= N) return;

    // ---- stage 1: h = in @ W1 + b1 (packed pairs over the 16 outputs) ----
    unsigned long long hp[8];
#pragma unroll
    for (int j = 0; j < 8; j++) PACK_F32X2(hp[j], b1s[2 * j], b1s[2 * j + 1]);

    const float* src0 = x + (size_t)n * KF;
    const float* src1 = g_scratch + (size_t)n * KF;
    const float* src2 = g_scratch + (size_t)(NNODES + n) * KF;

    for (int s = 0; s < 3; s++) {
        const float4* sp4 = (const float4*)((s == 0) ? src0 : (s == 1) ? src1 : src2);
        for (int c = 0; c < 12; c++) {
            float4 v = sp4[c];
            // 4 input rows starting at (s*48 + 4c); each row = 16 f32 = 4 ull2
            const ulonglong2* w =
                (const ulonglong2*)&W1s[(s * 48 + c * 4) * 16];
            const float vv[4] = {v.x, v.y, v.z, v.w};
#pragma unroll
            for (int r = 0; r < 4; r++) {
                unsigned long long a;
                PACK_F32X2(a, vv[r], vv[r]);
#pragma unroll
                for (int u = 0; u < 4; u++) {
                    ulonglong2 wb = w[4 * r + u];
                    FMA_F32X2(hp[2 * u + 0], a, wb.x);
                    FMA_F32X2(hp[2 * u + 1], a, wb.y);
                }
            }
        }
    }

    float h[16];
#pragma unroll
    for (int j = 0; j < 8; j++) UNPACK_F32X2(h[2 * j], h[2 * j + 1], hp[j]);
#pragma unroll
    for (int j = 0; j < 16; j++) h[j] = tanhf(h[j]);

    // ---- stage 2: C = h @ W2 + b2 (24 packed pairs over the 48 outputs) ----
    unsigned long long Cp[24];
#pragma unroll
    for (int p = 0; p < 24; p++) PACK_F32X2(Cp[p], b2s[2 * p], b2s[2 * p + 1]);

#pragma unroll
    for (int j = 0; j < 16; j++) {
        unsigned long long a;
        PACK_F32X2(a, h[j], h[j]);
        const ulonglong2* w = (const ulonglong2*)&W2s[j * 48]; // 12 ull2
#pragma unroll
        for (int u = 0; u < 12; u++) {
            ulonglong2 wb = w[u];
            FMA_F32X2(Cp[2 * u + 0], a, wb.x);
            FMA_F32X2(Cp[2 * u + 1], a, wb.y);
        }
    }

    float C[48];
#pragma unroll
    for (int p = 0; p < 24; p++) UNPACK_F32X2(C[2 * p], C[2 * p + 1], Cp[p]);

    // ---- softmax over 48 columns ----
    float m = C[0];
#pragma unroll
    for (int c = 1; c < 48; c++) m = fmaxf(m, C[c]);
    float sum = 0.f;
#pragma unroll
    for (int c = 0; c < 48; c++) { C[c] = __expf(C[c] - m); sum += C[c]; }
    float inv = 1.0f / sum;
#pragma unroll
    for (int c = 0; c < 48; c++) C[c] *= inv;

    float4* o4 = (float4*)(out + (size_t)n * KF);
#pragma unroll
    for (int c = 0; c < 12; c++)
        o4[c] = make_float4(C[4 * c], C[4 * c + 1], C[4 * c + 2], C[4 * c + 3]);
}

// ---------------------------------------------------------------------------
// Launch
// ---------------------------------------------------------------------------
extern "C" void kernel_launch(void* const* d_in, const int* in_sizes, int n_in,
                              void* d_out, int out_size) {
    const float* x   = (const float*)d_in[0];
    const void*  pos = d_in[1];
    const void*  neg = d_in[2];
    const float* W1  = (const float*)d_in[3];
    const float* b1  = (const float*)d_in[4];
    const float* W2  = (const float*)d_in[5];
    const float* b2  = (const float*)d_in[6];
    float* out = (float*)d_out;

    int N = in_sizes[0] / KF;          // 100000
    int E = in_sizes[1] / 2;           // 1600000

    // 1) zero accumulators + probe index dtype
    int n4 = 2 * NNODES * KF / 4;
    zero_probe_kernel<<<(n4 + 255) / 256, 256>>>((const unsigned int*)pos, E, n4);

    // 2) scatter-add both edge sets (4 lanes / edge)
    long long total = 2LL * E * 4;
    int blocks = (int)((total + 255) / 256);
    scatter_kernel<<<blocks, 256>>>(x, pos, neg, E);

    // 3) fused MLP + softmax per node
    node_kernel<<<(N + 127) / 128, 128>>>(x, W1, b1, W2, b2, out, N);
}